// round 12
// baseline (speedup 1.0000x reference)
#include <cuda_runtime.h>
#include <cstdint>

// ---------------------------------------------------------------------------
// SeqExperts: out[n,e,f] = sum_d in[n,e,d] * W[e,d,f] + b[e,f]
// N=131072, E=8, D=128.
// mma.sync m16n8k8 tf32; A and W each RNA-rounded once (rel_err 2.988e-4).
// R11: W served as fragment-major LDG.64.nc from L1D (no W smem tile);
//      A staged LDG->rna->STS two chunks ahead (no inner-loop cvt);
//      smem = 2 x 16KB A buffers only.
// ---------------------------------------------------------------------------

#define N_TOK 131072
#define E_EXP 8
#define D_DIM 128

// Fragment-major W: [e][g=16][nfg=16][lane=32] float2
//   lane = 4q + r holds ( W[d=8g+r][f=8nfg+q], W[d=8g+r+4][f=8nfg+q] )
static __device__ __align__(16) float g_Wf[E_EXP * 16 * 16 * 32 * 2];

__device__ __forceinline__ float rna_tf32(float v) {
    uint32_t u;
    asm("cvt.rna.tf32.f32 %0, %1;" : "=r"(u) : "f"(v));
    return __uint_as_float(u);
}

// ---------------- prep: W -> fragment-major, RNA-rounded ----------------
__global__ void prep_w_kernel(const float* __restrict__ W) {
    int i = blockIdx.x * blockDim.x + threadIdx.x;   // 131072, coalesced read
    int e = i >> 14;
    int d = (i >> 7) & 127;
    int f = i & 127;
    int g   = d >> 3;
    int r   = d & 3;
    int s   = (d >> 2) & 1;
    int nfg = f >> 3;
    int q   = f & 7;
    int idx = ((((e << 4) + g) << 4) + nfg) * 64 + ((q << 2) + r) * 2 + s;
    g_Wf[idx] = rna_tf32(W[i]);
}

// ---------------- mma.sync wrapper ----------------
__device__ __forceinline__ void mma1688(float c[4], float a0, float a1,
                                        float a2, float a3, float b0, float b1) {
    asm volatile(
        "mma.sync.aligned.m16n8k8.row.col.f32.tf32.tf32.f32 "
        "{%0,%1,%2,%3}, {%4,%5,%6,%7}, {%8,%9}, {%0,%1,%2,%3};"
        : "+f"(c[0]), "+f"(c[1]), "+f"(c[2]), "+f"(c[3])
        : "r"(__float_as_uint(a0)), "r"(__float_as_uint(a1)),
          "r"(__float_as_uint(a2)), "r"(__float_as_uint(a3)),
          "r"(__float_as_uint(b0)), "r"(__float_as_uint(b1)));
}

// A buffers: 2 x (128 rows x 32 floats), 16B-unit swizzle u' = u ^ (m&7)
#define ABUF_FLOATS 4096

// ---------------- main kernel ----------------
__global__ void __launch_bounds__(256, 2)
moe_hmma_kernel(const float* __restrict__ A,
                const float* __restrict__ bias,
                float* __restrict__ out) {
    __shared__ float smbuf[2 * ABUF_FLOATS];   // 32 KB

    const int tid  = threadIdx.x;
    const int wid  = tid >> 5;
    const int lane = tid & 31;
    const int e    = blockIdx.y;
    const int n0   = blockIdx.x << 7;
    const int q    = lane >> 2;
    const int r    = lane & 3;
    const int warpM = (wid & 3) << 5;    // 0,32,64,96
    const int warpN = (wid >> 2) << 6;   // 0,64

    // staging ids: unit j = tid&7 (16B within row), base row = tid>>3 (+32i)
    const int sj  = tid & 7;
    const int sm0 = tid >> 3;
    const int sjs = sj ^ (sm0 & 7);                 // swizzled 16B unit
    const char* abase = (const char*)A + (size_t)n0 * 4096 + (size_t)e * 512;

    // per-lane W fragment base (float2 units)
    const float2* wf = (const float2*)g_Wf + ((size_t)e << 13)
                       + ((wid >> 2) << 8) + lane;

    float4 v[4];   // staging regs (one chunk: 4 rows x 16B per thread)

    // ---- staging helpers (macros to keep regs tight) ----
    #define LDG_CHUNK(kb)                                                     \
        _Pragma("unroll")                                                     \
        for (int i = 0; i < 4; ++i)                                           \
            v[i] = *(const float4*)(abase + (size_t)(sm0 + (i << 5)) * 4096   \
                                    + ((kb) << 7) + (sj << 4));

    #define RND_STS(bufidx)                                                   \
        _Pragma("unroll")                                                     \
        for (int i = 0; i < 4; ++i) {                                         \
            float4 h;                                                         \
            h.x = rna_tf32(v[i].x); h.y = rna_tf32(v[i].y);                   \
            h.z = rna_tf32(v[i].z); h.w = rna_tf32(v[i].w);                   \
            *(float4*)(smbuf + (bufidx) * ABUF_FLOATS                         \
                       + ((sm0 + (i << 5)) << 5) + (sjs << 2)) = h;           \
        }

    // ---- prologue: chunk0 -> buf0; chunk1 into regs ----
    LDG_CHUNK(0);
    RND_STS(0);
    LDG_CHUNK(1);
    __syncthreads();

    float acc[2][8][4];
    #pragma unroll
    for (int mf = 0; mf < 2; ++mf)
        #pragma unroll
        for (int nf = 0; nf < 8; ++nf)
            #pragma unroll
            for (int c = 0; c < 4; ++c) acc[mf][nf][c] = 0.f;

    const int asw = q << 1;   // 8B-elt swizzle term for my fragment rows

    #pragma unroll
    for (int kb = 0; kb < 4; ++kb) {
        const float* Abuf = smbuf + (kb & 1) * ABUF_FLOATS;

        #pragma unroll
        for (int ks = 0; ks < 4; ++ks) {
            const int g = (kb << 2) + ks;

            // b-frags: 8 coalesced LDG.64 from L1-resident fragment-major W
            float2 b[8];
            #pragma unroll
            for (int nf = 0; nf < 8; ++nf)
                b[nf] = __ldg(wf + (g << 9) + (nf << 5));

            // a-frags: 8 conflict-free LDS.32 of pre-rounded values
            const int eb   = (ks << 2) + (r >> 1);
            const int half = r & 1;
            const int i0 = ((eb ^ asw) << 1) + half;
            const int i2 = (((eb + 2) ^ asw) << 1) + half;
            float a0[2], a1[2], a2[2], a3[2];
            #pragma unroll
            for (int mf = 0; mf < 2; ++mf) {
                const int m = warpM + (mf << 4) + q;
                const float* rp  = Abuf + (m << 5);
                const float* rp8 = rp + 256;      // +8 rows
                a0[mf] = rp[i0];
                a1[mf] = rp8[i0];
                a2[mf] = rp[i2];
                a3[mf] = rp8[i2];
            }

            #pragma unroll
            for (int mf = 0; mf < 2; ++mf)
                #pragma unroll
                for (int nf = 0; nf < 8; ++nf)
                    mma1688(acc[mf][nf], a0[mf], a1[mf], a2[mf], a3[mf],
                            b[nf].x, b[nf].y);
        }

        // stage next chunks: STS c(kb+1) (regs loaded one chunk ago), LDG c(kb+2)
        if (kb < 3) {
            RND_STS((kb + 1) & 1);
            if (kb < 2) LDG_CHUNK(kb + 2);
            __syncthreads();
        }
    }

    // ---- epilogue: + bias, float2 stores ----
    float bv[8][2];
    #pragma unroll
    for (int nf = 0; nf < 8; ++nf) {
        int f = warpN + (nf << 3) + (r << 1);
        bv[nf][0] = __ldg(bias + (e << 7) + f);
        bv[nf][1] = __ldg(bias + (e << 7) + f + 1);
    }

    #pragma unroll
    for (int mf = 0; mf < 2; ++mf) {
        int m0 = n0 + warpM + (mf << 4) + q;
        float* o0 = out + ((size_t)m0 << 10) + ((size_t)e << 7) + warpN + (r << 1);
        float* o1 = o0 + ((size_t)8 << 10);
        #pragma unroll
        for (int nf = 0; nf < 8; ++nf) {
            float2 v0 = { acc[mf][nf][0] + bv[nf][0], acc[mf][nf][1] + bv[nf][1] };
            float2 v1 = { acc[mf][nf][2] + bv[nf][0], acc[mf][nf][3] + bv[nf][1] };
            *(float2*)(o0 + (nf << 3)) = v0;
            *(float2*)(o1 + (nf << 3)) = v1;
        }
    }
}

// ---------------- launch ----------------
extern "C" void kernel_launch(void* const* d_in, const int* in_sizes, int n_in,
                              void* d_out, int out_size) {
    const float* A = (const float*)d_in[0];   // [N, E, D]
    const float* W = (const float*)d_in[1];   // [E, D, D]
    const float* b = (const float*)d_in[2];   // [E, D]
    float* out = (float*)d_out;               // [N, E, D]

    prep_w_kernel<<<E_EXP * D_DIM * D_DIM / 256, 256>>>(W);

    dim3 grid(N_TOK / 128, E_EXP);
    moe_hmma_kernel<<<grid, 256>>>(A, b, out);
}

// round 15
// speedup vs baseline: 1.1136x; 1.1136x over previous
#include <cuda_runtime.h>
#include <cstdint>

// ---------------------------------------------------------------------------
// SeqExperts: out[n,e,f] = sum_d in[n,e,d] * W[e,d,f] + b[e,f]
// N=131072, E=8, D=128.
// mma.sync m16n8k8 tf32; A and W each RNA-rounded once (rel_err 2.988e-4).
// R12: persistent CTAs (296 = 2/SM). Each CTA: contiguous block of ~28 tiles,
//      expert-major -> W smem tile loaded ~once per CTA; A chunks stream
//      through 3 rotating cp.async buffers across tile boundaries (pipeline
//      never drains). Inner loop identical to the 230us R10 kernel.
// ---------------------------------------------------------------------------

#define N_TOK 131072
#define E_EXP 8
#define D_DIM 128
#define NCTA  296          // 148 SMs x 2 resident CTAs
#define NTILE 8192         // 1024 token-tiles x 8 experts

// W pre-transposed + RNA-rounded + pair-interleaved: row (e,f) holds 64
// float2 pairs; pair p=4g+r holds (W[d], W[d+4]) with d=8g+r.
static __device__ __align__(16) float g_Wt[E_EXP * D_DIM * D_DIM];

__device__ __forceinline__ float rna_tf32(float v) {
    uint32_t u;
    asm("cvt.rna.tf32.f32 %0, %1;" : "=r"(u) : "f"(v));
    return __uint_as_float(u);
}

__device__ __forceinline__ uint32_t smem_u32(const void* p) {
    uint32_t a;
    asm("{ .reg .u64 t; cvta.to.shared.u64 t, %1; cvt.u32.u64 %0, t; }"
        : "=r"(a) : "l"(p));
    return a;
}

__device__ __forceinline__ void cp16(uint32_t dst, const void* src) {
    asm volatile("cp.async.cg.shared.global [%0], [%1], 16;"
                 :: "r"(dst), "l"(src) : "memory");
}
#define CP_COMMIT() asm volatile("cp.async.commit_group;" ::: "memory")
template <int N>
__device__ __forceinline__ void cp_wait() {
    asm volatile("cp.async.wait_group %0;" :: "n"(N) : "memory");
}

// ---------------- prep: transpose + round + pair-interleave W ----------------
__global__ void prep_w_kernel(const float* __restrict__ W) {
    int i = blockIdx.x * blockDim.x + threadIdx.x;   // 131072, coalesced read
    int e = i >> 14;
    int d = (i >> 7) & 127;
    int f = i & 127;
    int idx = ((d >> 3) << 3) + ((d & 3) << 1) + ((d >> 2) & 1);
    g_Wt[(((e << 7) | f) << 7) + idx] = rna_tf32(W[i]);
}

// ---------------- mma.sync wrapper ----------------
__device__ __forceinline__ void mma1688(float c[4], float a0, float a1,
                                        float a2, float a3, float b0, float b1) {
    asm volatile(
        "mma.sync.aligned.m16n8k8.row.col.f32.tf32.tf32.f32 "
        "{%0,%1,%2,%3}, {%4,%5,%6,%7}, {%8,%9}, {%0,%1,%2,%3};"
        : "+f"(c[0]), "+f"(c[1]), "+f"(c[2]), "+f"(c[3])
        : "r"(__float_as_uint(a0)), "r"(__float_as_uint(a1)),
          "r"(__float_as_uint(a2)), "r"(__float_as_uint(a3)),
          "r"(__float_as_uint(b0)), "r"(__float_as_uint(b1)));
}

// ---------------- SMEM layout (swizzled, no padding) ----------------
// W: 128 rows x 512B. 16B unit j at j ^ ((f&7)<<1).            64 KB
// A: 3 bufs of 128 rows x 128B. 16B unit j at j ^ (m&7).       16 KB each
#define SM_A0 (128 * 128)                         // float offset of A buf 0
#define ABUF_FLOATS (128 * 32)
#define SMEM_BYTES ((SM_A0 + 3 * ABUF_FLOATS) * 4)    // 114688 B

// ---------------- main kernel (persistent) ----------------
__global__ void __launch_bounds__(256, 2)
moe_hmma_kernel(const float* __restrict__ A,
                const float* __restrict__ bias,
                float* __restrict__ out) {
    extern __shared__ float sm[];
    float* Wsm = sm;

    const int tid  = threadIdx.x;
    const int wid  = tid >> 5;
    const int lane = tid & 31;
    const int q    = lane >> 2;
    const int r    = lane & 3;
    const int warpM = (wid & 3) << 5;    // 0,32,64,96
    const int warpN = (wid >> 2) << 6;   // 0,64

    const uint32_t sW = smem_u32(sm);
    const uint32_t sAb = sW + SM_A0 * 4;

    // staging ids
    const int sj  = tid & 7;             // 16B unit within 128B row-chunk
    const int sm0 = tid >> 3;            // base row (rows sm0 + 32i)
    const int sjs = sj ^ (sm0 & 7);      // swizzled 16B unit (row&7 == sm0&7)

    // tile range for this CTA (contiguous, expert-major: t = e*1024 + nb)
    const unsigned bid = blockIdx.x;
    const int t0 = (int)((bid * (unsigned)NTILE) / NCTA);
    const int t1 = (int)(((bid + 1) * (unsigned)NTILE) / NCTA);

    // chunk stream: sc = next chunk to compute, sp = next to prefetch
    int sc = t0 << 2;
    const int s_end = t1 << 2;
    int sp = sc;
    int ib = sc % 3;                     // buffer of chunk sc
    int ip = ib;                         // buffer of chunk sp

    // ---- prefetch helper ----
    #define PREFETCH(S, BUF) do {                                             \
        const int _t  = (S) >> 2;                                             \
        const int _kb = (S) & 3;                                              \
        const char* _src = (const char*)A                                     \
            + (size_t)((_t & 1023) << 7) * 4096                               \
            + (size_t)(_t >> 10) * 512 + (_kb << 7) + (sj << 4);              \
        const uint32_t _dst = sAb + (BUF) * (ABUF_FLOATS * 4)                 \
                              + (sjs << 4);                                   \
        _Pragma("unroll")                                                     \
        for (int _i = 0; _i < 4; ++_i)                                        \
            cp16(_dst + ((sm0 + (_i << 5)) << 7),                             \
                 _src + (size_t)(_i << 5) * 4096 + (size_t)sm0 * 4096);       \
        CP_COMMIT();                                                          \
    } while (0)

    // prologue: 2 chunks in flight
    PREFETCH(sp, ip); ++sp; ip = (ip + 1 == 3) ? 0 : ip + 1;
    PREFETCH(sp, ip); ++sp; ip = (ip + 1 == 3) ? 0 : ip + 1;

    int e_cur = -1;
    const int wsw = q << 2;              // W swizzle term for my rows
    const int asw = q << 1;              // A swizzle term for my rows

    for (int t = t0; t < t1; ++t) {
        const int e  = t >> 10;
        const int n0 = (t & 1023) << 7;

        // ---- (re)load W tile when expert changes (rare: ~1x per CTA) ----
        if (e != e_cur) {
            __syncthreads();             // all warps done reading old W
            const char* wsrc = (const char*)(g_Wt + (e << 14));
            #pragma unroll
            for (int i = 0; i < 16; ++i) {
                int u = tid + (i << 8);
                int f = u >> 5;
                int j = u & 31;
                int js = j ^ ((f & 7) << 1);
                *(float4*)((char*)Wsm + f * 512 + (js << 4)) =
                    *(const float4*)(wsrc + (size_t)f * 512 + (j << 4));
            }
            e_cur = e;
            __syncthreads();             // W visible to all
        }

        float acc[2][8][4];
        #pragma unroll
        for (int mf = 0; mf < 2; ++mf)
            #pragma unroll
            for (int nf = 0; nf < 8; ++nf)
                #pragma unroll
                for (int c = 0; c < 4; ++c) acc[mf][nf][c] = 0.f;

        #pragma unroll
        for (int kb = 0; kb < 4; ++kb) {
            // chunk sc must be complete
            if (sp - sc >= 2) cp_wait<1>(); else cp_wait<0>();
            __syncthreads();             // data visible; prev buf free

            // keep 2 chunks in flight (overlaps with compute below)
            if (sp < s_end) {
                PREFETCH(sp, ip);
                ++sp; ip = (ip + 1 == 3) ? 0 : ip + 1;
            }

            const float* Abuf = sm + SM_A0 + ib * ABUF_FLOATS;

            #pragma unroll
            for (int ks = 0; ks < 4; ++ks) {
                const int g = (kb << 2) + ks;

                float2 b[8];
                #pragma unroll
                for (int nf = 0; nf < 8; ++nf) {
                    int f  = warpN + (nf << 3) + q;
                    int ep = ((g << 2) + r) ^ wsw;
                    b[nf] = *(const float2*)(Wsm + (f << 7) + (ep << 1));
                }

                const int eb   = (ks << 2) + (r >> 1);
                const int half = r & 1;
                const int i0 = ((eb ^ asw) << 1) + half;
                const int i2 = (((eb + 2) ^ asw) << 1) + half;
                float a0[2], a1[2], a2[2], a3[2];
                #pragma unroll
                for (int mf = 0; mf < 2; ++mf) {
                    const int m = warpM + (mf << 4) + q;
                    const float* rp  = Abuf + (m << 5);
                    const float* rp8 = rp + 256;
                    a0[mf] = rp[i0];
                    a1[mf] = rp8[i0];
                    a2[mf] = rp[i2];
                    a3[mf] = rp8[i2];
                }

                #pragma unroll
                for (int mf = 0; mf < 2; ++mf)
                    #pragma unroll
                    for (int nf = 0; nf < 8; ++nf)
                        mma1688(acc[mf][nf], a0[mf], a1[mf], a2[mf], a3[mf],
                                b[nf].x, b[nf].y);
            }

            ++sc; ib = (ib + 1 == 3) ? 0 : ib + 1;
        }

        // ---- epilogue for tile t: + bias, float2 stores ----
        float bv[8][2];
        #pragma unroll
        for (int nf = 0; nf < 8; ++nf) {
            int f = warpN + (nf << 3) + (r << 1);
            bv[nf][0] = __ldg(bias + (e << 7) + f);
            bv[nf][1] = __ldg(bias + (e << 7) + f + 1);
        }

        #pragma unroll
        for (int mf = 0; mf < 2; ++mf) {
            int m0 = n0 + warpM + (mf << 4) + q;
            float* o0 = out + ((size_t)m0 << 10) + ((size_t)e << 7)
                        + warpN + (r << 1);
            float* o1 = o0 + ((size_t)8 << 10);
            #pragma unroll
            for (int nf = 0; nf < 8; ++nf) {
                float2 v0 = { acc[mf][nf][0] + bv[nf][0],
                              acc[mf][nf][1] + bv[nf][1] };
                float2 v1 = { acc[mf][nf][2] + bv[nf][0],
                              acc[mf][nf][3] + bv[nf][1] };
                *(float2*)(o0 + (nf << 3)) = v0;
                *(float2*)(o1 + (nf << 3)) = v1;
            }
        }
    }
    #undef PREFETCH
}

// ---------------- launch ----------------
extern "C" void kernel_launch(void* const* d_in, const int* in_sizes, int n_in,
                              void* d_out, int out_size) {
    const float* A = (const float*)d_in[0];   // [N, E, D]
    const float* W = (const float*)d_in[1];   // [E, D, D]
    const float* b = (const float*)d_in[2];   // [E, D]
    float* out = (float*)d_out;               // [N, E, D]

    cudaFuncSetAttribute(moe_hmma_kernel,
                         cudaFuncAttributeMaxDynamicSharedMemorySize, SMEM_BYTES);

    prep_w_kernel<<<E_EXP * D_DIM * D_DIM / 256, 256>>>(W);

    moe_hmma_kernel<<<NCTA, 256, SMEM_BYTES>>>(A, b, out);
}

// round 17
// speedup vs baseline: 1.3240x; 1.1890x over previous
#include <cuda_runtime.h>
#include <cstdint>

// ---------------------------------------------------------------------------
// SeqExperts: out[n,e,f] = sum_d in[n,e,d] * W[e,d,f] + b[e,f]
// N=131072, E=8, D=128.
// mma.sync m16n8k8 tf32; W RNA-rounded once (prep kernel); A fed raw (HW
// truncation) -> measured rel_err 4.67e-4 < 1e-3.
// R15 = R10 (230us) + (a) no inner-loop A rounding, (b) per-half (128-thread)
// named barriers: warps 0-3 own token rows 0-63, warps 4-7 rows 64-127; each
// half stages its own rows of each chunk -> no full-CTA convergence in loop.
// ---------------------------------------------------------------------------

#define N_TOK 131072
#define E_EXP 8
#define D_DIM 128

// W pre-transposed + RNA-rounded + pair-interleaved: row (e,f) holds 64
// float2 pairs; pair p=4g+r holds (W[d], W[d+4]) with d=8g+r.
static __device__ __align__(16) float g_Wt[E_EXP * D_DIM * D_DIM];

__device__ __forceinline__ float rna_tf32(float v) {
    uint32_t u;
    asm("cvt.rna.tf32.f32 %0, %1;" : "=r"(u) : "f"(v));
    return __uint_as_float(u);
}

__device__ __forceinline__ uint32_t smem_u32(const void* p) {
    uint32_t a;
    asm("{ .reg .u64 t; cvta.to.shared.u64 t, %1; cvt.u32.u64 %0, t; }"
        : "=r"(a) : "l"(p));
    return a;
}

__device__ __forceinline__ void cp16(uint32_t dst, const void* src) {
    asm volatile("cp.async.cg.shared.global [%0], [%1], 16;"
                 :: "r"(dst), "l"(src) : "memory");
}
#define CP_COMMIT() asm volatile("cp.async.commit_group;" ::: "memory")
template <int N>
__device__ __forceinline__ void cp_wait() {
    asm volatile("cp.async.wait_group %0;" :: "n"(N) : "memory");
}
__device__ __forceinline__ void bar_half(int id) {
    asm volatile("bar.sync %0, 128;" :: "r"(id) : "memory");
}

// ---------------- prep: transpose + round + pair-interleave W ----------------
__global__ void prep_w_kernel(const float* __restrict__ W) {
    int i = blockIdx.x * blockDim.x + threadIdx.x;   // 131072, coalesced read
    int e = i >> 14;
    int d = (i >> 7) & 127;
    int f = i & 127;
    int idx = ((d >> 3) << 3) + ((d & 3) << 1) + ((d >> 2) & 1);
    g_Wt[(((e << 7) | f) << 7) + idx] = rna_tf32(W[i]);
}

// ---------------- mma.sync wrapper ----------------
__device__ __forceinline__ void mma1688(float c[4], float a0, float a1,
                                        float a2, float a3, float b0, float b1) {
    asm volatile(
        "mma.sync.aligned.m16n8k8.row.col.f32.tf32.tf32.f32 "
        "{%0,%1,%2,%3}, {%4,%5,%6,%7}, {%8,%9}, {%0,%1,%2,%3};"
        : "+f"(c[0]), "+f"(c[1]), "+f"(c[2]), "+f"(c[3])
        : "r"(__float_as_uint(a0)), "r"(__float_as_uint(a1)),
          "r"(__float_as_uint(a2)), "r"(__float_as_uint(a3)),
          "r"(__float_as_uint(b0)), "r"(__float_as_uint(b1)));
}

// ---------------- SMEM layout (swizzled, no padding) ----------------
// W: 128 rows x 512B. 16B unit j at j ^ ((f&7)<<1).            64 KB
// A: 3 bufs of 128 rows x 128B. 16B unit j at j ^ (m&7).       16 KB each
#define SM_A0 (128 * 128)                        // float offset of A buf 0
#define ABUF_FLOATS (128 * 32)
#define SMEM_BYTES ((SM_A0 + 3 * ABUF_FLOATS) * 4)   // 114688 B

// ---------------- main kernel ----------------
__global__ void __launch_bounds__(256, 2)
moe_hmma_kernel(const float* __restrict__ A,
                const float* __restrict__ bias,
                float* __restrict__ out) {
    extern __shared__ float sm[];
    float* Wsm = sm;

    const int tid  = threadIdx.x;
    const int wid  = tid >> 5;
    const int lane = tid & 31;
    const int e    = blockIdx.y;
    const int n0   = blockIdx.x << 7;
    const int q    = lane >> 2;
    const int r    = lane & 3;

    // half-CTA decomposition: h owns token rows [h*64, h*64+64)
    const int h     = wid >> 2;               // 0 or 1
    const int w2    = wid & 3;
    const int warpM = (h << 6) + ((w2 & 1) << 5);   // h*64 + {0,32}
    const int warpN = (w2 >> 1) << 6;               // 0 or 64

    const uint32_t sW  = smem_u32(sm);
    const uint32_t sAb = sW + SM_A0 * 4;

    // per-half staging ids: 128 threads load this half's 64 rows per chunk
    const int t128 = tid & 127;
    const char* abase = (const char*)A + (size_t)n0 * 4096 + (size_t)e * 512;

    // prefetch chunk KB of this half's rows into buffer BUF
    #define PREFETCH(KB, BUF) do {                                            \
        _Pragma("unroll")                                                     \
        for (int _i = 0; _i < 4; ++_i) {                                      \
            int _u  = t128 + (_i << 7);        /* 0..511 16B units */         \
            int _lr = _u >> 3;                 /* local row 0..63 */          \
            int _j  = _u & 7;                                                 \
            int _m  = (h << 6) + _lr;                                         \
            int _js = _j ^ (_m & 7);                                          \
            cp16(sAb + (BUF) * (ABUF_FLOATS * 4) + (_m << 7) + (_js << 4),    \
                 abase + (size_t)_m * 4096 + ((KB) << 7) + (_j << 4));        \
        }                                                                     \
        CP_COMMIT();                                                          \
    } while (0)

    // ---- prologue: W quarter + chunk0(half) = group0; chunk1(half) = group1
    {
        const char* wsrc = (const char*)(g_Wt + (e << 14));
        #pragma unroll
        for (int i = 0; i < 16; ++i) {
            int u = tid + (i << 8);               // 0..4095 16B units
            int f = u >> 5;
            int j = u & 31;
            int js = j ^ ((f & 7) << 1);
            cp16(sW + f * 512 + (js << 4), wsrc + (size_t)f * 512 + (j << 4));
        }
    }
    PREFETCH(0, 0);                               // group 0 (with W)
    PREFETCH(1, 1);                               // group 1

    float acc[2][8][4];
    #pragma unroll
    for (int mf = 0; mf < 2; ++mf)
        #pragma unroll
        for (int nf = 0; nf < 8; ++nf)
            #pragma unroll
            for (int c = 0; c < 4; ++c) acc[mf][nf][c] = 0.f;

    const int wsw = q << 2;      // W swizzle term for my fragment rows
    const int asw = q << 1;      // A swizzle term for my fragment rows

    #pragma unroll
    for (int kb = 0; kb < 4; ++kb) {
        // chunk kb complete for this thread's copies
        if (kb < 3) cp_wait<1>(); else cp_wait<0>();
        if (kb == 0) __syncthreads();             // W written by all 256
        else bar_half(1 + h);                     // half-scope convergence

        // keep pipeline full: prefetch chunk kb+2 into buffer (kb+2)%3
        if (kb < 2) PREFETCH(kb + 2, (kb + 2) % 3);

        const float* Abuf = sm + SM_A0 + (kb % 3) * ABUF_FLOATS;

        #pragma unroll
        for (int ks = 0; ks < 4; ++ks) {
            const int g = (kb << 2) + ks;

            float2 b[8];
            #pragma unroll
            for (int nf = 0; nf < 8; ++nf) {
                int f  = warpN + (nf << 3) + q;
                int ep = ((g << 2) + r) ^ wsw;
                b[nf] = *(const float2*)(Wsm + (f << 7) + (ep << 1));
            }

            const int eb = (ks << 2) + (r >> 1);
            const int hf = r & 1;
            const int i0 = ((eb ^ asw) << 1) + hf;
            const int i2 = (((eb + 2) ^ asw) << 1) + hf;
            float a0[2], a1[2], a2[2], a3[2];
            #pragma unroll
            for (int mf = 0; mf < 2; ++mf) {
                const int m = warpM + (mf << 4) + q;
                const float* rp  = Abuf + (m << 5);
                const float* rp8 = rp + 256;
                a0[mf] = rp[i0];                  // raw fp32: HW tf32-truncates
                a1[mf] = rp8[i0];
                a2[mf] = rp[i2];
                a3[mf] = rp8[i2];
            }

            #pragma unroll
            for (int mf = 0; mf < 2; ++mf)
                #pragma unroll
                for (int nf = 0; nf < 8; ++nf)
                    mma1688(acc[mf][nf], a0[mf], a1[mf], a2[mf], a3[mf],
                            b[nf].x, b[nf].y);
        }
    }
    #undef PREFETCH

    // ---- epilogue: + bias, float2 stores ----
    float bv[8][2];
    #pragma unroll
    for (int nf = 0; nf < 8; ++nf) {
        int f = warpN + (nf << 3) + (r << 1);
        bv[nf][0] = __ldg(bias + (e << 7) + f);
        bv[nf][1] = __ldg(bias + (e << 7) + f + 1);
    }

    #pragma unroll
    for (int mf = 0; mf < 2; ++mf) {
        int m0 = n0 + warpM + (mf << 4) + q;
        float* o0 = out + ((size_t)m0 << 10) + ((size_t)e << 7) + warpN + (r << 1);
        float* o1 = o0 + ((size_t)8 << 10);
        #pragma unroll
        for (int nf = 0; nf < 8; ++nf) {
            float2 v0 = { acc[mf][nf][0] + bv[nf][0], acc[mf][nf][1] + bv[nf][1] };
            float2 v1 = { acc[mf][nf][2] + bv[nf][0], acc[mf][nf][3] + bv[nf][1] };
            *(float2*)(o0 + (nf << 3)) = v0;
            *(float2*)(o1 + (nf << 3)) = v1;
        }
    }
}

// ---------------- launch ----------------
extern "C" void kernel_launch(void* const* d_in, const int* in_sizes, int n_in,
                              void* d_out, int out_size) {
    const float* A = (const float*)d_in[0];   // [N, E, D]
    const float* W = (const float*)d_in[1];   // [E, D, D]
    const float* b = (const float*)d_in[2];   // [E, D]
    float* out = (float*)d_out;               // [N, E, D]

    cudaFuncSetAttribute(moe_hmma_kernel,
                         cudaFuncAttributeMaxDynamicSharedMemorySize, SMEM_BYTES);

    prep_w_kernel<<<E_EXP * D_DIM * D_DIM / 256, 256>>>(W);

    dim3 grid(N_TOK / 128, E_EXP);
    moe_hmma_kernel<<<grid, 256, SMEM_BYTES>>>(A, b, out);
}